// round 1
// baseline (speedup 1.0000x reference)
#include <cuda_runtime.h>
#include <cstdint>

#define Bsz 1024
#define Tt  128
#define Dd  64
#define Hh  256
#define MB  8            // batch rows per CTA
#define NTHREADS 256
#define GRID (Bsz / MB)  // 128 CTAs

// ---------------- shared memory layout (≈196 KB, 1 CTA/SM) -----------------
struct __align__(16) Smem {
    float hist[Hh * Dd];         // hist_W (256,64) row-major        16384
    float tdxT[Dd * Dd];         // td_x_W^T: [k][j] = td_x_W[j][k]   4096
    float frT[Dd * Dd];          // fr_W^T:   [k][j] = fr_W[j][k]     4096
    float wc[2 * Dd * Dd];       // wc_W (128,64) row-major           8192
    float hp[(MB / 2) * Hh * 2]; // h paired: hp[p*512 + k*2 + par]   2048
    float cs[MB * Hh];           // c state [r][k]                    2048
    float zp[(MB / 2) * 4 * Hh * 2]; // gate acts paired by row       8192
    float xs[MB * Dd];           //                                    512
    float ms[MB * Dd];           //                                    512
    float mp[(MB / 2) * Dd * 2]; // m paired                           512
    float ds[MB * Dd];           //                                    512
    float gx[MB * Dd];           // gamma_x                            512
    float xc[MB * Dd];           // x_c                                512
    float ccp[(MB / 2) * Dd * 2];// c_c paired                         512
    float tdh_b[Hh];
    float tdx_b[Dd];
    float hist_b[Dd];
    float fr_b[Dd];
    float wc_b[Dd];
    float lstm_b[4 * Hh];        //                                   1024
};

typedef unsigned long long u64;

__device__ __forceinline__ u64 dup2(float w) {
    u64 r; asm("mov.b64 %0, {%1,%1};" : "=l"(r) : "f"(w)); return r;
}
__device__ __forceinline__ void upk2(u64 v, float& lo, float& hi) {
    asm("mov.b64 {%0,%1}, %2;" : "=f"(lo), "=f"(hi) : "l"(v));
}
__device__ __forceinline__ u64 fma2(u64 a, u64 b, u64 c) {
    u64 d; asm("fma.rn.f32x2 %0, %1, %2, %3;" : "=l"(d) : "l"(a), "l"(b), "l"(c)); return d;
}
__device__ __forceinline__ float sigf(float x) {
    return __fdividef(1.f, 1.f + __expf(-x));
}
__device__ __forceinline__ float tanhfast(float x) {
    return __fdividef(2.f, 1.f + __expf(-2.f * x)) - 1.f;
}

__global__ void __launch_bounds__(NTHREADS, 1) rits_kernel(
    const float* __restrict__ values, const float* __restrict__ masks,
    const float* __restrict__ deltas,
    const float* __restrict__ tdhW, const float* __restrict__ tdhB,
    const float* __restrict__ tdxW, const float* __restrict__ tdxB,
    const float* __restrict__ histW, const float* __restrict__ histB,
    const float* __restrict__ frW, const float* __restrict__ frB,
    const float* __restrict__ wcW, const float* __restrict__ wcB,
    const float* __restrict__ lstmK, const float* __restrict__ lstmRK,
    const float* __restrict__ lstmB,
    const float* __restrict__ outW, const float* __restrict__ outB,
    float* __restrict__ yout, float* __restrict__ impout)
{
    extern __shared__ char smem_raw[];
    Smem& sm = *reinterpret_cast<Smem*>(smem_raw);

    const int t  = threadIdx.x;
    const int b0 = blockIdx.x * MB;

    // ---- stage resident weights/biases once ----
    for (int e = t; e < Hh * Dd; e += NTHREADS) sm.hist[e] = histW[e];
    for (int e = t; e < Dd * Dd; e += NTHREADS) {
        int k = e >> 6, jj = e & 63;
        sm.tdxT[e] = tdxW[jj * Dd + k];
        sm.frT[e]  = frW[jj * Dd + k];
    }
    for (int e = t; e < 2 * Dd * Dd; e += NTHREADS) sm.wc[e] = wcW[e];
    for (int e = t; e < Hh; e += NTHREADS) sm.tdh_b[e] = tdhB[e];
    if (t < Dd) {
        sm.tdx_b[t] = tdxB[t]; sm.hist_b[t] = histB[t];
        sm.fr_b[t]  = frB[t];  sm.wc_b[t]   = wcB[t];
    }
    for (int e = t; e < 4 * Hh; e += NTHREADS) sm.lstm_b[e] = lstmB[e];
    for (int e = t; e < MB * Hh; e += NTHREADS) sm.cs[e] = 0.f;
    for (int e = t; e < (MB / 2) * Hh * 2; e += NTHREADS) sm.hp[e] = 0.f;
    __syncthreads();

    const int j  = t & 63;   // feature column for D-wide phases
    const int rp = t >> 6;   // row-pair id 0..3 (also gate id in LSTM phase)
    const int r0 = rp * 2, r1 = r0 + 1;

    for (int step = 0; step < Tt; ++step) {
        // -------- A: load x/m/d tiles --------
        for (int e = t; e < MB * Dd; e += NTHREADS) {
            int r = e >> 6, jj = e & 63;
            int off = ((b0 + r) * Tt + step) * Dd + jj;
            float xv = values[off], mv = masks[off], dv = deltas[off];
            sm.xs[e] = xv; sm.ms[e] = mv; sm.ds[e] = dv;
            sm.mp[(r >> 1) * 128 + jj * 2 + (r & 1)] = mv;
        }
        __syncthreads();

        // -------- B: gamma_h = exp(-relu(d @ td_h_W^T + b)); h *= gamma_h ----
        {
            float acc[MB];
            #pragma unroll
            for (int r = 0; r < MB; r++) acc[r] = 0.f;
            const float4* w4 = (const float4*)(tdhW + t * Dd);
            #pragma unroll 4
            for (int k4 = 0; k4 < 16; k4++) {
                float4 w = w4[k4];
                #pragma unroll
                for (int r = 0; r < MB; r++) {
                    float4 d4 = ((const float4*)(sm.ds + r * Dd))[k4];
                    acc[r] += d4.x * w.x + d4.y * w.y + d4.z * w.z + d4.w * w.w;
                }
            }
            float bb = sm.tdh_b[t];
            #pragma unroll
            for (int p = 0; p < MB / 2; p++) {
                float2 hv = *(float2*)(sm.hp + p * 512 + t * 2);
                hv.x *= __expf(-fmaxf(acc[2 * p]     + bb, 0.f));
                hv.y *= __expf(-fmaxf(acc[2 * p + 1] + bb, 0.f));
                *(float2*)(sm.hp + p * 512 + t * 2) = hv;
            }
        }
        __syncthreads();

        // -------- C: x_h = h @ hist_W + b;  gamma_x;  x_c --------
        float xh0, xh1;
        {
            float a0 = sm.hist_b[j], a1 = a0;
            #pragma unroll 4
            for (int k = 0; k < Hh; k++) {
                float2 hv = *(const float2*)(sm.hp + rp * 512 + k * 2);
                float w = sm.hist[k * Dd + j];
                a0 += hv.x * w; a1 += hv.y * w;
            }
            xh0 = a0; xh1 = a1;
            float g0 = sm.tdx_b[j], g1 = g0;
            #pragma unroll 4
            for (int k = 0; k < Dd; k++) {
                float w = sm.tdxT[k * Dd + j];
                g0 += sm.ds[r0 * Dd + k] * w;
                g1 += sm.ds[r1 * Dd + k] * w;
            }
            g0 = __expf(-fmaxf(g0, 0.f));
            g1 = __expf(-fmaxf(g1, 0.f));
            sm.gx[r0 * Dd + j] = g0; sm.gx[r1 * Dd + j] = g1;
            float m0 = sm.ms[r0 * Dd + j], m1 = sm.ms[r1 * Dd + j];
            float x0 = sm.xs[r0 * Dd + j], x1 = sm.xs[r1 * Dd + j];
            sm.xc[r0 * Dd + j] = m0 * x0 + (1.f - m0) * xh0;
            sm.xc[r1 * Dd + j] = m1 * x1 + (1.f - m1) * xh1;
        }
        __syncthreads();

        // -------- D: z_h = x_c @ fr_W^T;  alpha;  c_h;  c_c (imputation) ----
        {
            float z0 = sm.fr_b[j], z1 = z0;
            float al0 = sm.wc_b[j], al1 = al0;
            #pragma unroll 4
            for (int k = 0; k < Dd; k++) {
                float wf = sm.frT[k * Dd + j];
                z0 += sm.xc[r0 * Dd + k] * wf;
                z1 += sm.xc[r1 * Dd + k] * wf;
                float wa = sm.wc[k * Dd + j];
                float wb = sm.wc[(Dd + k) * Dd + j];
                al0 += sm.gx[r0 * Dd + k] * wa + sm.ms[r0 * Dd + k] * wb;
                al1 += sm.gx[r1 * Dd + k] * wa + sm.ms[r1 * Dd + k] * wb;
            }
            float m0 = sm.ms[r0 * Dd + j], m1 = sm.ms[r1 * Dd + j];
            float x0 = sm.xs[r0 * Dd + j], x1 = sm.xs[r1 * Dd + j];
            float ch0 = al0 * z0 + (1.f - al0) * xh0;
            float ch1 = al1 * z1 + (1.f - al1) * xh1;
            float cc0 = m0 * x0 + (1.f - m0) * ch0;
            float cc1 = m1 * x1 + (1.f - m1) * ch1;
            sm.ccp[rp * 128 + j * 2 + 0] = cc0;
            sm.ccp[rp * 128 + j * 2 + 1] = cc1;
            impout[((b0 + r0) * Tt + step) * Dd + j] = cc0;
            impout[((b0 + r1) * Tt + step) * Dd + j] = cc1;
        }
        __syncthreads();

        // -------- E: z = [c_c,m] @ lstm_k + h @ lstm_rk + b; gate acts ------
        {
            u64 acc2[4][4];
            #pragma unroll
            for (int q = 0; q < 4; q++) {
                u64 b2 = dup2(sm.lstm_b[4 * t + q]);
                #pragma unroll
                for (int p = 0; p < 4; p++) acc2[p][q] = b2;
            }
            // recurrent part: k over H=256
            const float4* rk4 = (const float4*)lstmRK;
            for (int k = 0; k < Hh; k += 2) {
                float4 w0 = rk4[k * 256 + t];
                float4 w1 = rk4[(k + 1) * 256 + t];
                u64 wd0[4] = {dup2(w0.x), dup2(w0.y), dup2(w0.z), dup2(w0.w)};
                u64 wd1[4] = {dup2(w1.x), dup2(w1.y), dup2(w1.z), dup2(w1.w)};
                #pragma unroll
                for (int p = 0; p < 4; p++) {
                    float4 hv = *(const float4*)(sm.hp + p * 512 + k * 2);
                    u64 h0 = ((const u64*)&hv)[0];
                    u64 h1 = ((const u64*)&hv)[1];
                    #pragma unroll
                    for (int q = 0; q < 4; q++) {
                        acc2[p][q] = fma2(h0, wd0[q], acc2[p][q]);
                        acc2[p][q] = fma2(h1, wd1[q], acc2[p][q]);
                    }
                }
            }
            // input part 1: c_c (k 0..63)
            const float4* kk4 = (const float4*)lstmK;
            for (int k = 0; k < Dd; k += 2) {
                float4 w0 = kk4[k * 256 + t];
                float4 w1 = kk4[(k + 1) * 256 + t];
                u64 wd0[4] = {dup2(w0.x), dup2(w0.y), dup2(w0.z), dup2(w0.w)};
                u64 wd1[4] = {dup2(w1.x), dup2(w1.y), dup2(w1.z), dup2(w1.w)};
                #pragma unroll
                for (int p = 0; p < 4; p++) {
                    float4 hv = *(const float4*)(sm.ccp + p * 128 + k * 2);
                    u64 h0 = ((const u64*)&hv)[0];
                    u64 h1 = ((const u64*)&hv)[1];
                    #pragma unroll
                    for (int q = 0; q < 4; q++) {
                        acc2[p][q] = fma2(h0, wd0[q], acc2[p][q]);
                        acc2[p][q] = fma2(h1, wd1[q], acc2[p][q]);
                    }
                }
            }
            // input part 2: m (k 64..127)
            for (int k = 0; k < Dd; k += 2) {
                float4 w0 = kk4[(Dd + k) * 256 + t];
                float4 w1 = kk4[(Dd + k + 1) * 256 + t];
                u64 wd0[4] = {dup2(w0.x), dup2(w0.y), dup2(w0.z), dup2(w0.w)};
                u64 wd1[4] = {dup2(w1.x), dup2(w1.y), dup2(w1.z), dup2(w1.w)};
                #pragma unroll
                for (int p = 0; p < 4; p++) {
                    float4 hv = *(const float4*)(sm.mp + p * 128 + k * 2);
                    u64 h0 = ((const u64*)&hv)[0];
                    u64 h1 = ((const u64*)&hv)[1];
                    #pragma unroll
                    for (int q = 0; q < 4; q++) {
                        acc2[p][q] = fma2(h0, wd0[q], acc2[p][q]);
                        acc2[p][q] = fma2(h1, wd1[q], acc2[p][q]);
                    }
                }
            }
            // activations (gate id = t>>6: i,f sigmoid; g tanh; o sigmoid)
            const int gate = t >> 6;
            #pragma unroll
            for (int p = 0; p < 4; p++) {
                #pragma unroll
                for (int q = 0; q < 4; q++) {
                    float v0, v1; upk2(acc2[p][q], v0, v1);
                    float a0, a1;
                    if (gate == 2) { a0 = tanhfast(v0); a1 = tanhfast(v1); }
                    else           { a0 = sigf(v0);     a1 = sigf(v1);     }
                    int col = 4 * t + q;
                    *(float2*)(sm.zp + p * 2048 + col * 2) = make_float2(a0, a1);
                }
            }
        }
        __syncthreads();

        // -------- F: c = f*c + i*g ; h = o*tanh(c) --------
        {
            int r = t >> 5;
            int p = r >> 1, par = r & 1;
            int c0 = (t & 31) * 8;
            #pragma unroll
            for (int cc = 0; cc < 8; cc++) {
                int c = c0 + cc;
                float iv = sm.zp[p * 2048 + (0 * Hh + c) * 2 + par];
                float fv = sm.zp[p * 2048 + (1 * Hh + c) * 2 + par];
                float gv = sm.zp[p * 2048 + (2 * Hh + c) * 2 + par];
                float ov = sm.zp[p * 2048 + (3 * Hh + c) * 2 + par];
                float cold = sm.cs[r * Hh + c];
                float cnew = fv * cold + iv * gv;
                sm.cs[r * Hh + c] = cnew;
                sm.hp[p * 512 + c * 2 + par] = ov * tanhfast(cnew);
            }
        }
        __syncthreads();
    }

    // -------- final: y = h @ out_W + out_b --------
    {
        int w = t >> 5, lane = t & 31;
        if (w < MB) {
            float s = 0.f;
            for (int k = lane; k < Hh; k += 32)
                s += sm.hp[(w >> 1) * 512 + k * 2 + (w & 1)] * outW[k];
            #pragma unroll
            for (int o = 16; o > 0; o >>= 1)
                s += __shfl_down_sync(0xffffffffu, s, o);
            if (lane == 0) yout[b0 + w] = s + outB[0];
        }
    }
}

extern "C" void kernel_launch(void* const* d_in, const int* in_sizes, int n_in,
                              void* d_out, int out_size) {
    const float* values = (const float*)d_in[0];
    const float* masks  = (const float*)d_in[1];
    const float* deltas = (const float*)d_in[2];
    const float* tdhW   = (const float*)d_in[3];
    const float* tdhB   = (const float*)d_in[4];
    const float* tdxW   = (const float*)d_in[5];
    const float* tdxB   = (const float*)d_in[6];
    const float* histW  = (const float*)d_in[7];
    const float* histB  = (const float*)d_in[8];
    const float* frW    = (const float*)d_in[9];
    const float* frB    = (const float*)d_in[10];
    const float* wcW    = (const float*)d_in[11];
    const float* wcB    = (const float*)d_in[12];
    const float* lstmK  = (const float*)d_in[13];
    const float* lstmRK = (const float*)d_in[14];
    const float* lstmB  = (const float*)d_in[15];
    const float* outW   = (const float*)d_in[16];
    const float* outB   = (const float*)d_in[17];

    float* yout   = (float*)d_out;           // y_h: [B,1] first
    float* impout = yout + Bsz;              // imputations [B,T,D] after

    cudaFuncSetAttribute(rits_kernel, cudaFuncAttributeMaxDynamicSharedMemorySize,
                         (int)sizeof(Smem));
    rits_kernel<<<GRID, NTHREADS, sizeof(Smem)>>>(
        values, masks, deltas, tdhW, tdhB, tdxW, tdxB, histW, histB,
        frW, frB, wcW, wcB, lstmK, lstmRK, lstmB, outW, outB, yout, impout);
}

// round 2
// speedup vs baseline: 1.0985x; 1.0985x over previous
#include <cuda_runtime.h>
#include <cstdint>

#define Bsz 1024
#define Tt  128
#define Dd  64
#define Hh  256
#define MB  8
#define NT  512
#define GRID 128

typedef unsigned long long u64;

// transposed td_h_W: [k][c] (k in 0..63, c in 0..255), built by prologue kernel
__device__ float tdhT_g[Dd * Hh];

struct __align__(16) Smem {
    float hist[Hh * Dd];     // [k][j] (as given)            64 KB
    float tdxT[Dd * Dd];     // [k][j]                       16 KB
    float frT[Dd * Dd];      // [k][j]                       16 KB
    float wc[2 * Dd * Dd];   // [k][j]                       32 KB
    float hp[4 * 2 * Hh];    // h paired [p][k*2+par]         8 KB
    float cs[MB * Hh];       // c state                       8 KB
    float zp[4 * 2 * 4 * Hh];// gate acts [p][col*2+par]     32 KB (aliased as cpart in phase C)
    float xs[MB * Dd], ms[MB * Dd];
    float mp[4 * 2 * Dd], dp[4 * 2 * Dd];          // paired m, d
    float gxp[4 * 2 * Dd], alp[4 * 2 * Dd];        // paired gamma_x, alpha
    float xcp[4 * 2 * Dd], xhp[4 * 2 * Dd], ccp[4 * 2 * Dd];
    float tdh_b[Hh], tdx_b[Dd], hist_b[Dd], fr_b[Dd], wc_b[Dd], lstm_b[4 * Hh];
};

__device__ __forceinline__ u64 dup2(float w) {
    u64 r; asm("mov.b64 %0, {%1,%1};" : "=l"(r) : "f"(w)); return r;
}
__device__ __forceinline__ void upk2(u64 v, float& lo, float& hi) {
    asm("mov.b64 {%0,%1}, %2;" : "=f"(lo), "=f"(hi) : "l"(v));
}
__device__ __forceinline__ u64 fma2(u64 a, u64 b, u64 c) {
    u64 d; asm("fma.rn.f32x2 %0, %1, %2, %3;" : "=l"(d) : "l"(a), "l"(b), "l"(c)); return d;
}
__device__ __forceinline__ float sigf(float x) {
    return __fdividef(1.f, 1.f + __expf(-x));
}
__device__ __forceinline__ float tanhfast(float x) {
    return __fdividef(2.f, 1.f + __expf(-2.f * x)) - 1.f;
}

__global__ void transpose_tdh_kernel(const float* __restrict__ w) {
    int idx = blockIdx.x * 256 + threadIdx.x;   // 16384 elements
    int c = idx >> 6, k = idx & 63;
    tdhT_g[k * Hh + c] = w[idx];
}

__global__ void __launch_bounds__(NT, 1) rits_kernel(
    const float* __restrict__ values, const float* __restrict__ masks,
    const float* __restrict__ deltas,
    const float* __restrict__ tdhB,
    const float* __restrict__ tdxW, const float* __restrict__ tdxB,
    const float* __restrict__ histW, const float* __restrict__ histB,
    const float* __restrict__ frW, const float* __restrict__ frB,
    const float* __restrict__ wcW, const float* __restrict__ wcB,
    const float* __restrict__ lstmK, const float* __restrict__ lstmRK,
    const float* __restrict__ lstmB,
    const float* __restrict__ outW, const float* __restrict__ outB,
    float* __restrict__ yout, float* __restrict__ impout)
{
    extern __shared__ char smem_raw[];
    Smem& sm = *reinterpret_cast<Smem*>(smem_raw);

    const int t  = threadIdx.x;
    const int b0 = blockIdx.x * MB;

    // ---------------- stage resident weights & init state ----------------
    for (int e = t; e < Hh * Dd; e += NT) sm.hist[e] = histW[e];
    for (int e = t; e < Dd * Dd; e += NT) {
        int k = e >> 6, jj = e & 63;
        sm.tdxT[e] = tdxW[jj * Dd + k];
        sm.frT[e]  = frW[jj * Dd + k];
    }
    for (int e = t; e < 2 * Dd * Dd; e += NT) sm.wc[e] = wcW[e];
    for (int e = t; e < Hh; e += NT) sm.tdh_b[e] = tdhB[e];
    if (t < Dd) {
        sm.tdx_b[t] = tdxB[t]; sm.hist_b[t] = histB[t];
        sm.fr_b[t]  = frB[t];  sm.wc_b[t]   = wcB[t];
    }
    for (int e = t; e < 4 * Hh; e += NT) sm.lstm_b[e] = lstmB[e];
    for (int e = t; e < MB * Hh; e += NT) sm.cs[e] = 0.f;
    for (int e = t; e < 4 * 2 * Hh; e += NT) sm.hp[e] = 0.f;

    // step-0 inputs: 512 threads load exactly one element each
    {
        int r = t >> 6, jj = t & 63;
        int off = ((b0 + r) * Tt + 0) * Dd + jj;
        float xv = values[off], mv = masks[off], dv = deltas[off];
        sm.xs[t] = xv; sm.ms[t] = mv;
        sm.mp[(r >> 1) * 128 + jj * 2 + (r & 1)] = mv;
        sm.dp[(r >> 1) * 128 + jj * 2 + (r & 1)] = dv;
    }
    __syncthreads();

    float pf_x[2], pf_m[2], pf_d[2];   // prefetch registers (wg1)

    for (int step = 0; step < Tt; ++step) {
        // ============ S1: [wg0] gamma_h + h decay ∥ [wg1] gamma_x -> alpha
        if (t < 256) {
            const int c = t;
            u64 a[4];
            #pragma unroll
            for (int p = 0; p < 4; p++) a[p] = 0ULL;
            #pragma unroll 4
            for (int k = 0; k < Dd; k++) {
                u64 wd = dup2(tdhT_g[k * Hh + c]);
                #pragma unroll
                for (int p = 0; p < 4; p++) {
                    u64 d2 = *(const u64*)(sm.dp + p * 128 + k * 2);
                    a[p] = fma2(d2, wd, a[p]);
                }
            }
            float bb = sm.tdh_b[c];
            #pragma unroll
            for (int p = 0; p < 4; p++) {
                float a0, a1; upk2(a[p], a0, a1);
                float g0 = __expf(-fmaxf(a0 + bb, 0.f));
                float g1 = __expf(-fmaxf(a1 + bb, 0.f));
                float2 hv = *(float2*)(sm.hp + p * 512 + c * 2);
                hv.x *= g0; hv.y *= g1;
                *(float2*)(sm.hp + p * 512 + c * 2) = hv;
            }
        } else {
            const int u = t - 256;
            const int j = u & 63, rp = u >> 6;
            // gamma_x (paired rows)
            u64 g = dup2(sm.tdx_b[j]);
            #pragma unroll 4
            for (int k = 0; k < Dd; k++) {
                u64 wd = dup2(sm.tdxT[k * Dd + j]);
                u64 d2 = *(const u64*)(sm.dp + rp * 128 + k * 2);
                g = fma2(d2, wd, g);
            }
            float g0, g1; upk2(g, g0, g1);
            g0 = __expf(-fmaxf(g0, 0.f));
            g1 = __expf(-fmaxf(g1, 0.f));
            *(float2*)(sm.gxp + rp * 128 + j * 2) = make_float2(g0, g1);
            asm volatile("bar.sync 1, 256;" ::: "memory");
            // alpha = [gamma_x, m] @ wc + b   (gxp/mp with j role -> k)
            u64 al = dup2(sm.wc_b[j]);
            #pragma unroll 4
            for (int k = 0; k < Dd; k++) {
                u64 wa = dup2(sm.wc[k * Dd + j]);
                u64 wb = dup2(sm.wc[(Dd + k) * Dd + j]);
                u64 g2 = *(const u64*)(sm.gxp + rp * 128 + k * 2);
                u64 m2 = *(const u64*)(sm.mp  + rp * 128 + k * 2);
                al = fma2(g2, wa, al);
                al = fma2(m2, wb, al);
            }
            float a0, a1; upk2(al, a0, a1);
            *(float2*)(sm.alp + rp * 128 + j * 2) = make_float2(a0, a1);
        }
        __syncthreads();

        // ============ C: x_h = h @ hist_W (k-split 8-way), partials in zp ===
        float2* cpart = (float2*)sm.zp;    // [kq*4+p][j]
        {
            const int j = t & 63, kq = t >> 6;
            u64 a[4];
            #pragma unroll
            for (int p = 0; p < 4; p++) a[p] = 0ULL;
            const int k0 = kq * 32;
            #pragma unroll 4
            for (int kk = 0; kk < 32; kk++) {
                int k = k0 + kk;
                u64 wd = dup2(sm.hist[k * Dd + j]);
                #pragma unroll
                for (int p = 0; p < 4; p++) {
                    u64 h2 = *(const u64*)(sm.hp + p * 512 + k * 2);
                    a[p] = fma2(h2, wd, a[p]);
                }
            }
            #pragma unroll
            for (int p = 0; p < 4; p++) {
                float a0, a1; upk2(a[p], a0, a1);
                cpart[(kq * 4 + p) * 64 + j] = make_float2(a0, a1);
            }
        }
        __syncthreads();
        // reduce partials -> x_h, x_c (each thread one (row, col))
        {
            const int j = t & 63, p = (t >> 6) & 3, par = t >> 8;
            const float* cp = (const float*)cpart;
            float s = 0.f;
            #pragma unroll
            for (int kq = 0; kq < 8; kq++)
                s += cp[((kq * 4 + p) * 64 + j) * 2 + par];
            float xh = s + sm.hist_b[j];
            int r = 2 * p + par;
            float m = sm.ms[r * Dd + j], x = sm.xs[r * Dd + j];
            float xc = m * x + (1.f - m) * xh;
            sm.xcp[p * 128 + j * 2 + par] = xc;
            sm.xhp[p * 128 + j * 2 + par] = xh;
        }
        __syncthreads();

        // ============ D: [wg0] z_h -> c_h -> c_c (+imputation out)
        //              [wg1] prefetch next step inputs ======================
        if (t < 256) {
            const int j = t & 63, rp = t >> 6;
            u64 z = dup2(sm.fr_b[j]);
            #pragma unroll 4
            for (int k = 0; k < Dd; k++) {
                u64 wf = dup2(sm.frT[k * Dd + j]);
                u64 x2 = *(const u64*)(sm.xcp + rp * 128 + k * 2);
                z = fma2(x2, wf, z);
            }
            float z0, z1; upk2(z, z0, z1);
            float2 al = *(const float2*)(sm.alp + rp * 128 + j * 2);
            float2 xh = *(const float2*)(sm.xhp + rp * 128 + j * 2);
            int r0 = 2 * rp, r1 = r0 + 1;
            float m0 = sm.ms[r0 * Dd + j], m1 = sm.ms[r1 * Dd + j];
            float x0 = sm.xs[r0 * Dd + j], x1 = sm.xs[r1 * Dd + j];
            float ch0 = al.x * z0 + (1.f - al.x) * xh.x;
            float ch1 = al.y * z1 + (1.f - al.y) * xh.y;
            float cc0 = m0 * x0 + (1.f - m0) * ch0;
            float cc1 = m1 * x1 + (1.f - m1) * ch1;
            *(float2*)(sm.ccp + rp * 128 + j * 2) = make_float2(cc0, cc1);
            impout[((b0 + r0) * Tt + step) * Dd + j] = cc0;
            impout[((b0 + r1) * Tt + step) * Dd + j] = cc1;
        } else if (step + 1 < Tt) {
            const int u = t - 256;
            #pragma unroll
            for (int s = 0; s < 2; s++) {
                int e = u + s * 256;
                int r = e >> 6, jj = e & 63;
                int off = ((b0 + r) * Tt + (step + 1)) * Dd + jj;
                pf_x[s] = values[off]; pf_m[s] = masks[off]; pf_d[s] = deltas[off];
            }
        }
        __syncthreads();

        // ============ E: z = [c_c,m]@lstm_k + h@lstm_rk + b; activations ====
        {
            u64 acc[4][2];
            float bq0 = sm.lstm_b[2 * t], bq1 = sm.lstm_b[2 * t + 1];
            #pragma unroll
            for (int p = 0; p < 4; p++) { acc[p][0] = dup2(bq0); acc[p][1] = dup2(bq1); }

            const float2* rk2 = (const float2*)lstmRK;
            #pragma unroll 2
            for (int k = 0; k < Hh; k += 2) {
                float2 w0 = rk2[k * 512 + t];
                float2 w1 = rk2[(k + 1) * 512 + t];
                u64 wa0 = dup2(w0.x), wb0 = dup2(w0.y);
                u64 wa1 = dup2(w1.x), wb1 = dup2(w1.y);
                #pragma unroll
                for (int p = 0; p < 4; p++) {
                    float4 hv = *(const float4*)(sm.hp + p * 512 + k * 2);
                    u64 h0 = ((const u64*)&hv)[0];
                    u64 h1 = ((const u64*)&hv)[1];
                    acc[p][0] = fma2(h0, wa0, acc[p][0]);
                    acc[p][1] = fma2(h0, wb0, acc[p][1]);
                    acc[p][0] = fma2(h1, wa1, acc[p][0]);
                    acc[p][1] = fma2(h1, wb1, acc[p][1]);
                }
            }
            const float2* kk2 = (const float2*)lstmK;
            #pragma unroll 2
            for (int k = 0; k < Dd; k += 2) {
                float2 w0 = kk2[k * 512 + t];
                float2 w1 = kk2[(k + 1) * 512 + t];
                u64 wa0 = dup2(w0.x), wb0 = dup2(w0.y);
                u64 wa1 = dup2(w1.x), wb1 = dup2(w1.y);
                #pragma unroll
                for (int p = 0; p < 4; p++) {
                    float4 cv = *(const float4*)(sm.ccp + p * 128 + k * 2);
                    u64 c0 = ((const u64*)&cv)[0];
                    u64 c1 = ((const u64*)&cv)[1];
                    acc[p][0] = fma2(c0, wa0, acc[p][0]);
                    acc[p][1] = fma2(c0, wb0, acc[p][1]);
                    acc[p][0] = fma2(c1, wa1, acc[p][0]);
                    acc[p][1] = fma2(c1, wb1, acc[p][1]);
                }
            }
            #pragma unroll 2
            for (int k = 0; k < Dd; k += 2) {
                float2 w0 = kk2[(Dd + k) * 512 + t];
                float2 w1 = kk2[(Dd + k + 1) * 512 + t];
                u64 wa0 = dup2(w0.x), wb0 = dup2(w0.y);
                u64 wa1 = dup2(w1.x), wb1 = dup2(w1.y);
                #pragma unroll
                for (int p = 0; p < 4; p++) {
                    float4 mv = *(const float4*)(sm.mp + p * 128 + k * 2);
                    u64 m0 = ((const u64*)&mv)[0];
                    u64 m1 = ((const u64*)&mv)[1];
                    acc[p][0] = fma2(m0, wa0, acc[p][0]);
                    acc[p][1] = fma2(m0, wb0, acc[p][1]);
                    acc[p][0] = fma2(m1, wa1, acc[p][0]);
                    acc[p][1] = fma2(m1, wb1, acc[p][1]);
                }
            }
            const int gate = t >> 7;   // cols 2t,2t+1 share a gate
            #pragma unroll
            for (int p = 0; p < 4; p++) {
                #pragma unroll
                for (int q = 0; q < 2; q++) {
                    float v0, v1; upk2(acc[p][q], v0, v1);
                    float a0, a1;
                    if (gate == 2) { a0 = tanhfast(v0); a1 = tanhfast(v1); }
                    else           { a0 = sigf(v0);     a1 = sigf(v1);     }
                    int col = 2 * t + q;
                    *(float2*)(sm.zp + p * 2048 + col * 2) = make_float2(a0, a1);
                }
            }
        }
        __syncthreads();

        // ============ F: [wg0] c,h update  [wg1] store prefetched inputs ====
        if (t < 256) {
            int r = t >> 5;
            int p = r >> 1, par = r & 1;
            int c0 = (t & 31) * 8;
            #pragma unroll
            for (int cc = 0; cc < 8; cc++) {
                int c = c0 + cc;
                float iv = sm.zp[p * 2048 + (0 * Hh + c) * 2 + par];
                float fv = sm.zp[p * 2048 + (1 * Hh + c) * 2 + par];
                float gv = sm.zp[p * 2048 + (2 * Hh + c) * 2 + par];
                float ov = sm.zp[p * 2048 + (3 * Hh + c) * 2 + par];
                float cold = sm.cs[r * Hh + c];
                float cnew = fv * cold + iv * gv;
                sm.cs[r * Hh + c] = cnew;
                sm.hp[p * 512 + c * 2 + par] = ov * tanhfast(cnew);
            }
        } else if (step + 1 < Tt) {
            const int u = t - 256;
            #pragma unroll
            for (int s = 0; s < 2; s++) {
                int e = u + s * 256;
                int r = e >> 6, jj = e & 63;
                sm.xs[e] = pf_x[s]; sm.ms[e] = pf_m[s];
                sm.mp[(r >> 1) * 128 + jj * 2 + (r & 1)] = pf_m[s];
                sm.dp[(r >> 1) * 128 + jj * 2 + (r & 1)] = pf_d[s];
            }
        }
        __syncthreads();
    }

    // ---------------- final: y = h @ out_W + out_b ----------------
    {
        int w = t >> 5, lane = t & 31;
        if (w < MB) {
            float s = 0.f;
            for (int k = lane; k < Hh; k += 32)
                s += sm.hp[(w >> 1) * 512 + k * 2 + (w & 1)] * outW[k];
            #pragma unroll
            for (int o = 16; o > 0; o >>= 1)
                s += __shfl_down_sync(0xffffffffu, s, o);
            if (lane == 0) yout[b0 + w] = s + outB[0];
        }
    }
}

extern "C" void kernel_launch(void* const* d_in, const int* in_sizes, int n_in,
                              void* d_out, int out_size) {
    const float* values = (const float*)d_in[0];
    const float* masks  = (const float*)d_in[1];
    const float* deltas = (const float*)d_in[2];
    const float* tdhW   = (const float*)d_in[3];
    const float* tdhB   = (const float*)d_in[4];
    const float* tdxW   = (const float*)d_in[5];
    const float* tdxB   = (const float*)d_in[6];
    const float* histW  = (const float*)d_in[7];
    const float* histB  = (const float*)d_in[8];
    const float* frW    = (const float*)d_in[9];
    const float* frB    = (const float*)d_in[10];
    const float* wcW    = (const float*)d_in[11];
    const float* wcB    = (const float*)d_in[12];
    const float* lstmK  = (const float*)d_in[13];
    const float* lstmRK = (const float*)d_in[14];
    const float* lstmB  = (const float*)d_in[15];
    const float* outW   = (const float*)d_in[16];
    const float* outB   = (const float*)d_in[17];

    float* yout   = (float*)d_out;       // y_h [B,1] first
    float* impout = yout + Bsz;          // imputations [B,T,D]

    transpose_tdh_kernel<<<64, 256>>>(tdhW);

    cudaFuncSetAttribute(rits_kernel, cudaFuncAttributeMaxDynamicSharedMemorySize,
                         (int)sizeof(Smem));
    rits_kernel<<<GRID, NT, sizeof(Smem)>>>(
        values, masks, deltas, tdhB, tdxW, tdxB, histW, histB,
        frW, frB, wcW, wcB, lstmK, lstmRK, lstmB, outW, outB, yout, impout);
}